// round 11
// baseline (speedup 1.0000x reference)
#include <cuda_runtime.h>

// Attention_72447508349519 — algebraic collapse:
//   softmax rows sum to 1 and einsum('bqk,bvd->bqd') contracts k and v
//   independently, so out[b,q,d] = sum_n v[b,n,d] for every q.
//   Pipeline (3 kernels): k12 (stats+weighted colsums, last-CTA-per-batch
//   folds groups -> s) -> k3 (GEMV Wv) -> k4 (GEMV Wo + 64MB broadcast store).
//   Streaming hints (__ldcs on x / __stcs on out) keep Wv/Wo L2-resident
//   across graph replays (R10-proven, -4us).
// Unused inputs: Wq,bq,Wk,bk.

#define BSZ   16
#define CDIM  1024
#define NPOS  1024
#define NGRP  32
#define GROWS 32
#define EPS   1e-5f

__device__ float g_P[BSZ * NGRP * CDIM];
__device__ float g_mean[BSZ * NGRP];
__device__ float g_rstd[BSZ * NGRP];
__device__ float g_s[BSZ * CDIM];
__device__ float g_vsum[BSZ * CDIM];
__device__ int   g_cnt[BSZ];   // zero-init; each fold resets its slot -> replay-safe

// ---------------------------------------------------------------------------
// k12: phase A = R10 k1 (proven): per (b,g) CTA, one pass over the 1024x32
// slab of x; fj/gq lane mapping (every LDG.128 = 4 fully-used lines), MLP=8.
// Then last-arriving CTA of batch b runs the k2 fold in-place:
//   s[b,c] = sum_g rstd[b,g]*(P[b,g,c]-mean[b,g]*Gam_g) + sum_n beta[n]
// ---------------------------------------------------------------------------
#define PPITCH 1028   // bank = (4*fj + gq) mod 32 -> all 32 lanes distinct

__global__ __launch_bounds__(512) void k12_stats_fold(const float* __restrict__ x,
                                                      const float* __restrict__ gamma,
                                                      const float* __restrict__ beta) {
    const int b = blockIdx.x >> 5;
    const int g = blockIdx.x & 31;
    const int tid = threadIdx.x;

    __shared__ float sg[GROWS];
    __shared__ float spw[8 * PPITCH];     // 32.9 KB; reused as sgam in fold
    __shared__ float reds[16], redq[16];
    __shared__ int slast;

    if (tid < GROWS) sg[tid] = gamma[g * GROWS + tid];
    __syncthreads();

    const int fj = tid & 7;    // float4 slot within the 32-float group row
    const int gq = tid >> 3;   // channel base (c = gq + 64*k), 0..63
    const float w0 = sg[fj * 4 + 0], w1 = sg[fj * 4 + 1];
    const float w2 = sg[fj * 4 + 2], w3 = sg[fj * 4 + 3];

    const float* xb = x + (size_t)b * CDIM * NPOS + g * GROWS;
    float* mypw = spw + fj * PPITCH;

    float tsum = 0.f, tsq = 0.f;
    #pragma unroll
    for (int k0 = 0; k0 < 16; k0 += 8) {
        float4 t[8];
        #pragma unroll
        for (int i = 0; i < 8; i++) {
            const int c = gq + 64 * (k0 + i);
            t[i] = __ldcs(&reinterpret_cast<const float4*>(xb + (size_t)c * NPOS)[fj]);
        }
        #pragma unroll
        for (int i = 0; i < 8; i++) {
            const int c = gq + 64 * (k0 + i);
            const float4 v = t[i];
            tsum += (v.x + v.y) + (v.z + v.w);
            tsq  += (v.x * v.x + v.y * v.y) + (v.z * v.z + v.w * v.w);
            mypw[c] = w0 * v.x + w1 * v.y + w2 * v.z + w3 * v.w;
        }
    }
    __syncthreads();

    // Fold the 8 fj-partials per channel (conflict-free, stride-1 c).
    float* Pout = g_P + (b * NGRP + g) * CDIM;
    #pragma unroll
    for (int m = 0; m < 2; m++) {
        const int c = tid + 512 * m;
        float acc = spw[c];
        #pragma unroll
        for (int f = 1; f < 8; f++) acc += spw[f * PPITCH + c];
        Pout[c] = acc;
    }

    // Block reduction for mean/rstd.
    #pragma unroll
    for (int o = 16; o; o >>= 1) {
        tsum += __shfl_xor_sync(0xFFFFFFFFu, tsum, o);
        tsq  += __shfl_xor_sync(0xFFFFFFFFu, tsq,  o);
    }
    const int wid = tid >> 5, lane = tid & 31;
    if (lane == 0) { reds[wid] = tsum; redq[wid] = tsq; }
    __syncthreads();
    if (tid == 0) {
        float S = 0.f, Q = 0.f;
        #pragma unroll
        for (int w = 0; w < 16; w++) { S += reds[w]; Q += redq[w]; }
        const float inv = 1.f / (float)(GROWS * CDIM);
        const float m = S * inv;
        const float var = Q * inv - m * m;
        g_mean[b * NGRP + g] = m;
        g_rstd[b * NGRP + g] = rsqrtf(var + EPS);
    }

    // ---- last-CTA handoff (canonical threadFenceReduction pattern) ----
    __threadfence();                       // order this thread's P/mean writes
    __syncthreads();                       // all threads fenced before atomic
    if (tid == 0) slast = (atomicAdd(&g_cnt[b], 1) == NGRP - 1);
    __syncthreads();
    if (!slast) return;
    __threadfence();                       // acquire: see all 32 CTAs' writes

    // ---- fold phase (k2 body), 512 threads, smem reused ----
    float* sgam = spw;                     // alias: phase-A spw is dead
    __shared__ float sGam[NGRP], sm2[NGRP], sr2[NGRP];
    __shared__ float sB;

    sgam[tid]       = gamma[tid];
    sgam[tid + 512] = gamma[tid + 512];
    float bb = beta[tid] + beta[tid + 512];
    #pragma unroll
    for (int o = 16; o; o >>= 1) bb += __shfl_xor_sync(0xFFFFFFFFu, bb, o);
    if (lane == 0) reds[wid] = bb;
    if (tid < NGRP) { sm2[tid] = g_mean[b * NGRP + tid]; sr2[tid] = g_rstd[b * NGRP + tid]; }
    __syncthreads();

    if (tid < NGRP) {
        float t = 0.f;
        #pragma unroll
        for (int j = 0; j < GROWS; j++) t += sgam[tid * GROWS + j];
        sGam[tid] = t;
    }
    if (tid == 0) {
        float t = 0.f;
        #pragma unroll
        for (int w = 0; w < 16; w++) t += reds[w];
        sB = t;
        g_cnt[b] = 0;                      // reset for next graph replay
    }
    __syncthreads();

    #pragma unroll
    for (int m = 0; m < 2; m++) {
        const int c = tid + 512 * m;
        float acc = sB;
        const float* Pb = g_P + b * NGRP * CDIM + c;
        #pragma unroll
        for (int gg = 0; gg < NGRP; gg++)
            acc += sr2[gg] * (__ldcs(&Pb[gg * CDIM]) - sm2[gg] * sGam[gg]);
        g_s[b * CDIM + c] = acc;
    }
}

// ---------------------------------------------------------------------------
// k3: vsum[b,d] = s[b,:].Wv[d,:] + 1024*bv[d]
// grid (128 d-tiles, 8 batch-groups) = 1024 CTAs, 256 thr, 8KB smem.
// W default policy -> stays L2-resident across replays (x/out are streaming).
// ---------------------------------------------------------------------------
__global__ __launch_bounds__(256) void k3_gemv_v(const float* __restrict__ W,
                                                 const float* __restrict__ bias) {
    const int bg = blockIdx.y;           // batches 2*bg, 2*bg+1
    const int tid = threadIdx.x;
    const int wid = tid >> 5, lane = tid & 31;
    const int d = blockIdx.x * 8 + wid;

    __shared__ float ss[2 * CDIM];       // 8 KB

    const float4* wrow = reinterpret_cast<const float4*>(W + (size_t)d * CDIM);
    float4 wreg[8];
    #pragma unroll
    for (int j = 0; j < 8; j++) wreg[j] = wrow[lane + 32 * j];

    {
        const float4* src = reinterpret_cast<const float4*>(g_s + bg * 2 * CDIM);
        float4* dst = reinterpret_cast<float4*>(ss);
        #pragma unroll
        for (int m = 0; m < 2; m++) dst[tid + 256 * m] = src[tid + 256 * m];
    }
    __syncthreads();

    float acc[2] = {0.f, 0.f};
    #pragma unroll
    for (int j = 0; j < 8; j++) {
        const float4 wv = wreg[j];
        #pragma unroll
        for (int q = 0; q < 2; q++) {
            const float4 sv = reinterpret_cast<const float4*>(ss + q * CDIM)[lane + 32 * j];
            acc[q] += wv.x * sv.x + wv.y * sv.y + wv.z * sv.z + wv.w * sv.w;
        }
    }
    #pragma unroll
    for (int q = 0; q < 2; q++)
        #pragma unroll
        for (int o = 16; o; o >>= 1)
            acc[q] += __shfl_xor_sync(0xFFFFFFFFu, acc[q], o);

    if (lane == 0) {
        const float bs = (float)NPOS * bias[d];
        #pragma unroll
        for (int q = 0; q < 2; q++)
            g_vsum[(bg * 2 + q) * CDIM + d] = acc[q] + bs;
    }
}

// ---------------------------------------------------------------------------
// k4: y[b,d] = vsum[b,:].Wo[d,:] + bo[d], fused with the 64MB broadcast
// store out[b,d,:] = y[b,d] via __stcs. grid (128, 8) = 1024 CTAs.
// At its measured drain floor (~15.4us) — unchanged from R10.
// ---------------------------------------------------------------------------
__global__ __launch_bounds__(256) void k4_gemv_o_bcast(const float* __restrict__ W,
                                                       const float* __restrict__ bias,
                                                       float* __restrict__ out) {
    const int bg = blockIdx.y;           // batches 2*bg, 2*bg+1
    const int tid = threadIdx.x;
    const int wid = tid >> 5, lane = tid & 31;
    const int d = blockIdx.x * 8 + wid;

    __shared__ float ss[2 * CDIM];       // 8 KB

    const float4* wrow = reinterpret_cast<const float4*>(W + (size_t)d * CDIM);
    float4 wreg[8];
    #pragma unroll
    for (int j = 0; j < 8; j++) wreg[j] = wrow[lane + 32 * j];

    {
        const float4* src = reinterpret_cast<const float4*>(g_vsum + bg * 2 * CDIM);
        float4* dst = reinterpret_cast<float4*>(ss);
        #pragma unroll
        for (int m = 0; m < 2; m++) dst[tid + 256 * m] = src[tid + 256 * m];
    }
    __syncthreads();

    float acc[2] = {0.f, 0.f};
    #pragma unroll
    for (int j = 0; j < 8; j++) {
        const float4 wv = wreg[j];
        #pragma unroll
        for (int q = 0; q < 2; q++) {
            const float4 sv = reinterpret_cast<const float4*>(ss + q * CDIM)[lane + 32 * j];
            acc[q] += wv.x * sv.x + wv.y * sv.y + wv.z * sv.z + wv.w * sv.w;
        }
    }
    // Butterfly: every lane ends with the full sum -> whole warp streams stores.
    #pragma unroll
    for (int q = 0; q < 2; q++)
        #pragma unroll
        for (int o = 16; o; o >>= 1)
            acc[q] += __shfl_xor_sync(0xFFFFFFFFu, acc[q], o);

    const float bs = bias[d];
    #pragma unroll
    for (int q = 0; q < 2; q++) {
        const float v = acc[q] + bs;
        const float4 vv = make_float4(v, v, v, v);
        float4* row = reinterpret_cast<float4*>(
            out + ((size_t)((bg * 2 + q) * CDIM + d)) * NPOS);
        #pragma unroll
        for (int t = 0; t < 8; t++) __stcs(&row[lane + 32 * t], vv);
    }
}

extern "C" void kernel_launch(void* const* d_in, const int* in_sizes, int n_in,
                              void* d_out, int out_size) {
    const float* x     = (const float*)d_in[0];
    const float* gamma = (const float*)d_in[1];
    const float* beta  = (const float*)d_in[2];
    // d_in[3..6] = Wq,bq,Wk,bk : provably unused (softmax rows sum to 1).
    const float* Wv    = (const float*)d_in[7];
    const float* bv    = (const float*)d_in[8];
    const float* Wo    = (const float*)d_in[9];
    const float* bo    = (const float*)d_in[10];
    float* out = (float*)d_out;

    k12_stats_fold<<<BSZ * NGRP, 512>>>(x, gamma, beta);
    k3_gemv_v<<<dim3(CDIM / 8, 8), 256>>>(Wv, bv);
    k4_gemv_o_bcast<<<dim3(CDIM / 8, 8), 256>>>(Wo, bo, out);
}

// round 12
// speedup vs baseline: 1.0471x; 1.0471x over previous
#include <cuda_runtime.h>

// Attention_72447508349519 — algebraic collapse:
//   softmax rows sum to 1 and einsum('bqk,bvd->bqd') contracts k and v
//   independently, so out[b,q,d] = sum_n v[b,n,d] for every q.
//   Pipeline (3 kernels): k12 (stats+weighted colsums, last-CTA-per-batch
//   folds groups -> s) -> k3 (GEMV Wv) -> k4 (GEMV Wo + 64MB broadcast store).
//   R12 fix: __launch_bounds__(512, 2) on k12 — R11's merged fold let ptxas
//   take 126 regs -> 1 CTA/SM -> occ 25% and a latency-bound x stream.
//   Streaming hints (__ldcs on x / __stcs on out) keep Wv/Wo L2-resident
//   across graph replays (R10-proven).
// Unused inputs: Wq,bq,Wk,bk.

#define BSZ   16
#define CDIM  1024
#define NPOS  1024
#define NGRP  32
#define GROWS 32
#define EPS   1e-5f

__device__ float g_P[BSZ * NGRP * CDIM];
__device__ float g_mean[BSZ * NGRP];
__device__ float g_rstd[BSZ * NGRP];
__device__ float g_s[BSZ * CDIM];
__device__ float g_vsum[BSZ * CDIM];
__device__ int   g_cnt[BSZ];   // zero-init; each fold resets its slot -> replay-safe

// ---------------------------------------------------------------------------
// k12: phase A: per (b,g) CTA, one pass over the 1024x32 slab of x;
// fj/gq lane mapping (every LDG.128 = 4 fully-used lines), MLP=8 batches.
// Last-arriving CTA of batch b runs the fold in-place:
//   s[b,c] = sum_g rstd[b,g]*(P[b,g,c]-mean[b,g]*Gam_g) + sum_n beta[n]
// __launch_bounds__(512, 2): cap regs at 64 so 2 CTAs/SM stay resident
// (fold-path spills hit only 16 CTAs chip-wide).
// ---------------------------------------------------------------------------
#define PPITCH 1028   // bank = (4*fj + gq) mod 32 -> all 32 lanes distinct

__global__ __launch_bounds__(512, 2) void k12_stats_fold(const float* __restrict__ x,
                                                         const float* __restrict__ gamma,
                                                         const float* __restrict__ beta) {
    const int b = blockIdx.x >> 5;
    const int g = blockIdx.x & 31;
    const int tid = threadIdx.x;

    __shared__ float sg[GROWS];
    __shared__ float spw[8 * PPITCH];     // 32.9 KB; reused as sgam in fold
    __shared__ float reds[16], redq[16];
    __shared__ int slast;

    if (tid < GROWS) sg[tid] = gamma[g * GROWS + tid];
    __syncthreads();

    const int fj = tid & 7;    // float4 slot within the 32-float group row
    const int gq = tid >> 3;   // channel base (c = gq + 64*k), 0..63
    const float w0 = sg[fj * 4 + 0], w1 = sg[fj * 4 + 1];
    const float w2 = sg[fj * 4 + 2], w3 = sg[fj * 4 + 3];

    const float* xb = x + (size_t)b * CDIM * NPOS + g * GROWS;
    float* mypw = spw + fj * PPITCH;

    float tsum = 0.f, tsq = 0.f;
    #pragma unroll
    for (int k0 = 0; k0 < 16; k0 += 8) {
        float4 t[8];
        #pragma unroll
        for (int i = 0; i < 8; i++) {
            const int c = gq + 64 * (k0 + i);
            t[i] = __ldcs(&reinterpret_cast<const float4*>(xb + (size_t)c * NPOS)[fj]);
        }
        #pragma unroll
        for (int i = 0; i < 8; i++) {
            const int c = gq + 64 * (k0 + i);
            const float4 v = t[i];
            tsum += (v.x + v.y) + (v.z + v.w);
            tsq  += (v.x * v.x + v.y * v.y) + (v.z * v.z + v.w * v.w);
            mypw[c] = w0 * v.x + w1 * v.y + w2 * v.z + w3 * v.w;
        }
    }
    __syncthreads();

    // Fold the 8 fj-partials per channel (conflict-free, stride-1 c).
    float* Pout = g_P + (b * NGRP + g) * CDIM;
    #pragma unroll
    for (int m = 0; m < 2; m++) {
        const int c = tid + 512 * m;
        float acc = spw[c];
        #pragma unroll
        for (int f = 1; f < 8; f++) acc += spw[f * PPITCH + c];
        Pout[c] = acc;
    }

    // Block reduction for mean/rstd.
    #pragma unroll
    for (int o = 16; o; o >>= 1) {
        tsum += __shfl_xor_sync(0xFFFFFFFFu, tsum, o);
        tsq  += __shfl_xor_sync(0xFFFFFFFFu, tsq,  o);
    }
    const int wid = tid >> 5, lane = tid & 31;
    if (lane == 0) { reds[wid] = tsum; redq[wid] = tsq; }
    __syncthreads();
    if (tid == 0) {
        float S = 0.f, Q = 0.f;
        #pragma unroll
        for (int w = 0; w < 16; w++) { S += reds[w]; Q += redq[w]; }
        const float inv = 1.f / (float)(GROWS * CDIM);
        const float m = S * inv;
        const float var = Q * inv - m * m;
        g_mean[b * NGRP + g] = m;
        g_rstd[b * NGRP + g] = rsqrtf(var + EPS);
    }

    // ---- last-CTA handoff (canonical threadFenceReduction pattern) ----
    __threadfence();                       // order this thread's P/mean writes
    __syncthreads();                       // all threads fenced before atomic
    if (tid == 0) slast = (atomicAdd(&g_cnt[b], 1) == NGRP - 1);
    __syncthreads();
    if (!slast) return;
    __threadfence();                       // acquire: see all 32 CTAs' writes

    // ---- fold phase (k2 body), 512 threads, smem reused ----
    float* sgam = spw;                     // alias: phase-A spw is dead
    __shared__ float sGam[NGRP], sm2[NGRP], sr2[NGRP];
    __shared__ float sB;

    sgam[tid]       = gamma[tid];
    sgam[tid + 512] = gamma[tid + 512];
    float bb = beta[tid] + beta[tid + 512];
    #pragma unroll
    for (int o = 16; o; o >>= 1) bb += __shfl_xor_sync(0xFFFFFFFFu, bb, o);
    if (lane == 0) reds[wid] = bb;
    if (tid < NGRP) { sm2[tid] = g_mean[b * NGRP + tid]; sr2[tid] = g_rstd[b * NGRP + tid]; }
    __syncthreads();

    if (tid < NGRP) {
        float t = 0.f;
        #pragma unroll
        for (int j = 0; j < GROWS; j++) t += sgam[tid * GROWS + j];
        sGam[tid] = t;
    }
    if (tid == 0) {
        float t = 0.f;
        #pragma unroll
        for (int w = 0; w < 16; w++) t += reds[w];
        sB = t;
        g_cnt[b] = 0;                      // reset for next graph replay
    }
    __syncthreads();

    #pragma unroll
    for (int m = 0; m < 2; m++) {
        const int c = tid + 512 * m;
        float acc = sB;
        const float* Pb = g_P + b * NGRP * CDIM + c;
        #pragma unroll 8
        for (int gg = 0; gg < NGRP; gg++)
            acc += sr2[gg] * (__ldcs(&Pb[gg * CDIM]) - sm2[gg] * sGam[gg]);
        g_s[b * CDIM + c] = acc;
    }
}

// ---------------------------------------------------------------------------
// k3: vsum[b,d] = s[b,:].Wv[d,:] + 1024*bv[d]
// grid (128 d-tiles, 8 batch-groups) = 1024 CTAs, 256 thr, 8KB smem.
// W default policy -> stays L2-resident across replays (x/out are streaming).
// ---------------------------------------------------------------------------
__global__ __launch_bounds__(256) void k3_gemv_v(const float* __restrict__ W,
                                                 const float* __restrict__ bias) {
    const int bg = blockIdx.y;           // batches 2*bg, 2*bg+1
    const int tid = threadIdx.x;
    const int wid = tid >> 5, lane = tid & 31;
    const int d = blockIdx.x * 8 + wid;

    __shared__ float ss[2 * CDIM];       // 8 KB

    const float4* wrow = reinterpret_cast<const float4*>(W + (size_t)d * CDIM);
    float4 wreg[8];
    #pragma unroll
    for (int j = 0; j < 8; j++) wreg[j] = wrow[lane + 32 * j];

    {
        const float4* src = reinterpret_cast<const float4*>(g_s + bg * 2 * CDIM);
        float4* dst = reinterpret_cast<float4*>(ss);
        #pragma unroll
        for (int m = 0; m < 2; m++) dst[tid + 256 * m] = src[tid + 256 * m];
    }
    __syncthreads();

    float acc[2] = {0.f, 0.f};
    #pragma unroll
    for (int j = 0; j < 8; j++) {
        const float4 wv = wreg[j];
        #pragma unroll
        for (int q = 0; q < 2; q++) {
            const float4 sv = reinterpret_cast<const float4*>(ss + q * CDIM)[lane + 32 * j];
            acc[q] += wv.x * sv.x + wv.y * sv.y + wv.z * sv.z + wv.w * sv.w;
        }
    }
    #pragma unroll
    for (int q = 0; q < 2; q++)
        #pragma unroll
        for (int o = 16; o; o >>= 1)
            acc[q] += __shfl_xor_sync(0xFFFFFFFFu, acc[q], o);

    if (lane == 0) {
        const float bs = (float)NPOS * bias[d];
        #pragma unroll
        for (int q = 0; q < 2; q++)
            g_vsum[(bg * 2 + q) * CDIM + d] = acc[q] + bs;
    }
}

// ---------------------------------------------------------------------------
// k4: y[b,d] = vsum[b,:].Wo[d,:] + bo[d], fused with the 64MB broadcast
// store out[b,d,:] = y[b,d] via __stcs. grid (128, 8) = 1024 CTAs.
// At its measured drain floor (~15.4us).
// ---------------------------------------------------------------------------
__global__ __launch_bounds__(256) void k4_gemv_o_bcast(const float* __restrict__ W,
                                                       const float* __restrict__ bias,
                                                       float* __restrict__ out) {
    const int bg = blockIdx.y;           // batches 2*bg, 2*bg+1
    const int tid = threadIdx.x;
    const int wid = tid >> 5, lane = tid & 31;
    const int d = blockIdx.x * 8 + wid;

    __shared__ float ss[2 * CDIM];       // 8 KB

    const float4* wrow = reinterpret_cast<const float4*>(W + (size_t)d * CDIM);
    float4 wreg[8];
    #pragma unroll
    for (int j = 0; j < 8; j++) wreg[j] = wrow[lane + 32 * j];

    {
        const float4* src = reinterpret_cast<const float4*>(g_vsum + bg * 2 * CDIM);
        float4* dst = reinterpret_cast<float4*>(ss);
        #pragma unroll
        for (int m = 0; m < 2; m++) dst[tid + 256 * m] = src[tid + 256 * m];
    }
    __syncthreads();

    float acc[2] = {0.f, 0.f};
    #pragma unroll
    for (int j = 0; j < 8; j++) {
        const float4 wv = wreg[j];
        #pragma unroll
        for (int q = 0; q < 2; q++) {
            const float4 sv = reinterpret_cast<const float4*>(ss + q * CDIM)[lane + 32 * j];
            acc[q] += wv.x * sv.x + wv.y * sv.y + wv.z * sv.z + wv.w * sv.w;
        }
    }
    // Butterfly: every lane ends with the full sum -> whole warp streams stores.
    #pragma unroll
    for (int q = 0; q < 2; q++)
        #pragma unroll
        for (int o = 16; o; o >>= 1)
            acc[q] += __shfl_xor_sync(0xFFFFFFFFu, acc[q], o);

    const float bs = bias[d];
    #pragma unroll
    for (int q = 0; q < 2; q++) {
        const float v = acc[q] + bs;
        const float4 vv = make_float4(v, v, v, v);
        float4* row = reinterpret_cast<float4*>(
            out + ((size_t)((bg * 2 + q) * CDIM + d)) * NPOS);
        #pragma unroll
        for (int t = 0; t < 8; t++) __stcs(&row[lane + 32 * t], vv);
    }
}

extern "C" void kernel_launch(void* const* d_in, const int* in_sizes, int n_in,
                              void* d_out, int out_size) {
    const float* x     = (const float*)d_in[0];
    const float* gamma = (const float*)d_in[1];
    const float* beta  = (const float*)d_in[2];
    // d_in[3..6] = Wq,bq,Wk,bk : provably unused (softmax rows sum to 1).
    const float* Wv    = (const float*)d_in[7];
    const float* bv    = (const float*)d_in[8];
    const float* Wo    = (const float*)d_in[9];
    const float* bo    = (const float*)d_in[10];
    float* out = (float*)d_out;

    k12_stats_fold<<<BSZ * NGRP, 512>>>(x, gamma, beta);
    k3_gemv_v<<<dim3(CDIM / 8, 8), 256>>>(Wv, bv);
    k4_gemv_o_bcast<<<dim3(CDIM / 8, 8), 256>>>(Wo, bo, out);
}